// round 2
// baseline (speedup 1.0000x reference)
#include <cuda_runtime.h>

#define NN 50000
#define EE 800000
#define CC 128
#define GG 128
#define LD0 512
#define LD1 256
#define NC (NN*CC)

// ---------------- scratch (static device globals; no allocation) ----------------
__device__ int    g_deg[NN];
__device__ int    g_rowptr[NN + 1];
__device__ int    g_cursor[NN];
__device__ int    g_bsum[64];
__device__ int    g_boff[64];
__device__ float4 g_csr[EE];            // {src_as_float, ea0, ea1, ea2} in dst-CSR order
__device__ float  g_h[NN * CC];
__device__ float  g_h2[NN * CC];
__device__ float  g_qkvs[NN * CC * 4];  // planes: Q | K | V | S
__device__ float  g_pool[GG * CC];
__device__ float  g_m0[GG * LD0];
__device__ float  g_m1[GG * LD1];

// ---------------- CSR build ----------------
__global__ void k_zero_deg() {
    int i = blockIdx.x * blockDim.x + threadIdx.x;
    if (i < NN) g_deg[i] = 0;
}

__global__ void k_count(const int* __restrict__ dst) {
    int i = blockIdx.x * blockDim.x + threadIdx.x;
    if (i < EE) atomicAdd(&g_deg[dst[i]], 1);
}

__global__ void k_scan1() {
    __shared__ int s[1024];
    int i = blockIdx.x * 1024 + threadIdx.x;
    int v = (i < NN) ? g_deg[i] : 0;
    s[threadIdx.x] = v;
    __syncthreads();
    #pragma unroll
    for (int off = 1; off < 1024; off <<= 1) {
        int t = (threadIdx.x >= off) ? s[threadIdx.x - off] : 0;
        __syncthreads();
        s[threadIdx.x] += t;
        __syncthreads();
    }
    if (i < NN) g_rowptr[i + 1] = s[threadIdx.x];
    if (threadIdx.x == 1023) g_bsum[blockIdx.x] = s[1023];
    if (i == 0) g_rowptr[0] = 0;
}

__global__ void k_scan2(int nb) {
    int run = 0;
    for (int b = 0; b < nb; b++) { g_boff[b] = run; run += g_bsum[b]; }
}

__global__ void k_scan3() {
    int i = blockIdx.x * blockDim.x + threadIdx.x;
    if (i < NN) g_rowptr[i + 1] += g_boff[((unsigned)i) >> 10];
}

__global__ void k_cursor() {
    int i = blockIdx.x * blockDim.x + threadIdx.x;
    if (i < NN) g_cursor[i] = g_rowptr[i];
}

__global__ void k_fill(const int* __restrict__ src, const int* __restrict__ dst,
                       const float* __restrict__ ea) {
    int i = blockIdx.x * blockDim.x + threadIdx.x;
    if (i < EE) {
        int d = dst[i];
        int p = atomicAdd(&g_cursor[d], 1);
        g_csr[p] = make_float4(__int_as_float(src[i]), ea[3 * i], ea[3 * i + 1], ea[3 * i + 2]);
    }
}

// ---------------- layer-0 projection (din = 4) ----------------
__global__ __launch_bounds__(256) void k_proj0(
    const float* __restrict__ x,
    const float* __restrict__ Wq, const float* __restrict__ bq,
    const float* __restrict__ Wk, const float* __restrict__ bk,
    const float* __restrict__ Wv, const float* __restrict__ bv,
    const float* __restrict__ Ws, const float* __restrict__ bs)
{
    int idx = blockIdx.x * 256 + threadIdx.x;
    if (idx >= NN * 512) return;
    int n  = idx >> 9;
    int c  = idx & 511;
    int mat = c >> 7, cc = c & 127;
    const float* W = (mat == 0) ? Wq : (mat == 1) ? Wk : (mat == 2) ? Wv : Ws;
    const float* b = (mat == 0) ? bq : (mat == 1) ? bk : (mat == 2) ? bv : bs;
    float x0 = x[n * 4 + 0], x1 = x[n * 4 + 1], x2 = x[n * 4 + 2], x3 = x[n * 4 + 3];
    float v = b[cc];
    v = fmaf(x0, W[cc], v);
    v = fmaf(x1, W[128 + cc], v);
    v = fmaf(x2, W[256 + cc], v);
    v = fmaf(x3, W[384 + cc], v);
    g_qkvs[mat * NC + n * 128 + cc] = v;
}

// ---------------- fused 4-way projection SGEMM: [N,128] @ [128,128] x4 ----------------
// blockIdx.y selects which W (Q/K/V/S). 128x128 output tile, K=128 in 4 chunks of 32.
__global__ __launch_bounds__(256) void k_sgemm(
    int in_sel,
    const float* __restrict__ W0, const float* __restrict__ W1,
    const float* __restrict__ W2, const float* __restrict__ W3,
    const float* __restrict__ b0, const float* __restrict__ b1,
    const float* __restrict__ b2, const float* __restrict__ b3)
{
    const float* A = in_sel ? g_h2 : g_h;
    const float* B    = (blockIdx.y == 0) ? W0 : (blockIdx.y == 1) ? W1 : (blockIdx.y == 2) ? W2 : W3;
    const float* bias = (blockIdx.y == 0) ? b0 : (blockIdx.y == 1) ? b1 : (blockIdx.y == 2) ? b2 : b3;
    float* Out = g_qkvs + blockIdx.y * NC;

    __shared__ float As[32][132];   // transposed: As[k][m]
    __shared__ float Bs[32][128];   // Bs[k][n]

    int tid = threadIdx.x;
    int tx = tid & 15, ty = tid >> 4;
    int brow = blockIdx.x * 128;

    float acc[8][8];
    #pragma unroll
    for (int i = 0; i < 8; i++)
        #pragma unroll
        for (int j = 0; j < 8; j++) acc[i][j] = 0.f;

    for (int kk = 0; kk < 4; kk++) {
        // load A chunk: 128 rows x 32 k
        #pragma unroll
        for (int i = 0; i < 4; i++) {
            int idx = tid + i * 256;          // 0..1023
            int row = idx >> 3;               // 0..127
            int k4  = idx & 7;                // 0..7
            int gr = brow + row;
            float4 v = make_float4(0.f, 0.f, 0.f, 0.f);
            if (gr < NN) v = *reinterpret_cast<const float4*>(&A[gr * 128 + kk * 32 + k4 * 4]);
            As[k4 * 4 + 0][row] = v.x;
            As[k4 * 4 + 1][row] = v.y;
            As[k4 * 4 + 2][row] = v.z;
            As[k4 * 4 + 3][row] = v.w;
        }
        // load B chunk: 32 k x 128 cols
        #pragma unroll
        for (int i = 0; i < 4; i++) {
            int idx = tid + i * 256;
            int kr = idx >> 5;                // 0..31
            int n4 = idx & 31;                // 0..31
            float4 v = *reinterpret_cast<const float4*>(&B[(kk * 32 + kr) * 128 + n4 * 4]);
            *reinterpret_cast<float4*>(&Bs[kr][n4 * 4]) = v;
        }
        __syncthreads();

        #pragma unroll
        for (int k = 0; k < 32; k++) {
            float4 a0 = *reinterpret_cast<const float4*>(&As[k][ty * 8]);
            float4 a1 = *reinterpret_cast<const float4*>(&As[k][ty * 8 + 4]);
            float4 c0 = *reinterpret_cast<const float4*>(&Bs[k][tx * 8]);
            float4 c1 = *reinterpret_cast<const float4*>(&Bs[k][tx * 8 + 4]);
            float av[8] = {a0.x, a0.y, a0.z, a0.w, a1.x, a1.y, a1.z, a1.w};
            float bv[8] = {c0.x, c0.y, c0.z, c0.w, c1.x, c1.y, c1.z, c1.w};
            #pragma unroll
            for (int i = 0; i < 8; i++)
                #pragma unroll
                for (int j = 0; j < 8; j++)
                    acc[i][j] = fmaf(av[i], bv[j], acc[i][j]);
        }
        __syncthreads();
    }

    #pragma unroll
    for (int i = 0; i < 8; i++) {
        int r = brow + ty * 8 + i;
        if (r < NN) {
            #pragma unroll
            for (int j = 0; j < 8; j++) {
                int col = tx * 8 + j;
                Out[r * 128 + col] = acc[i][j] + bias[col];
            }
        }
    }
}

// ---------------- warp-per-node online-softmax aggregation ----------------
__global__ __launch_bounds__(256) void k_agg(const float* __restrict__ We, int out_sel)
{
    __shared__ float sWe[384];
    for (int i = threadIdx.x; i < 384; i += 256) sWe[i] = We[i];
    __syncthreads();

    int warp = threadIdx.x >> 5, lane = threadIdx.x & 31;
    int node = blockIdx.x * 8 + warp;
    if (node >= NN) return;

    float* hout = out_sel ? g_h2 : g_h;
    const float* Q = g_qkvs;
    const float* K = g_qkvs + NC;
    const float* V = g_qkvs + 2 * NC;
    const float* S = g_qkvs + 3 * NC;

    int o = node * 128;
    float q0 = Q[o + lane], q1 = Q[o + lane + 32], q2 = Q[o + lane + 64], q3 = Q[o + lane + 96];

    const float NEG_INF = __int_as_float(0xff800000);
    float m = NEG_INF, d = 0.f;
    float a0 = 0.f, a1 = 0.f, a2 = 0.f, a3 = 0.f;

    int beg = g_rowptr[node], end = g_rowptr[node + 1];

    float w0 = sWe[lane],       w1 = sWe[lane + 32],       w2 = sWe[lane + 64],       w3 = sWe[lane + 96];
    float u0 = sWe[128 + lane], u1 = sWe[160 + lane],      u2 = sWe[192 + lane],      u3 = sWe[224 + lane];
    float t0 = sWe[256 + lane], t1 = sWe[288 + lane],      t2 = sWe[320 + lane],      t3 = sWe[352 + lane];

    for (int e = beg; e < end; e++) {
        float4 ed = g_csr[e];
        int src = __float_as_int(ed.x);
        const float* Kr = K + src * 128;
        const float* Vr = V + src * 128;

        float e0 = fmaf(ed.y, w0, fmaf(ed.z, u0, ed.w * t0));
        float e1 = fmaf(ed.y, w1, fmaf(ed.z, u1, ed.w * t1));
        float e2 = fmaf(ed.y, w2, fmaf(ed.z, u2, ed.w * t2));
        float e3 = fmaf(ed.y, w3, fmaf(ed.z, u3, ed.w * t3));

        float k0 = Kr[lane] + e0, k1 = Kr[lane + 32] + e1, k2 = Kr[lane + 64] + e2, k3 = Kr[lane + 96] + e3;
        float v0 = Vr[lane] + e0, v1 = Vr[lane + 32] + e1, v2 = Vr[lane + 64] + e2, v3 = Vr[lane + 96] + e3;

        float p = fmaf(q0, k0, fmaf(q1, k1, fmaf(q2, k2, q3 * k3)));
        p += __shfl_xor_sync(0xffffffffu, p, 16);
        p += __shfl_xor_sync(0xffffffffu, p, 8);
        p += __shfl_xor_sync(0xffffffffu, p, 4);
        p += __shfl_xor_sync(0xffffffffu, p, 2);
        p += __shfl_xor_sync(0xffffffffu, p, 1);
        float logit = p * 0.08838834764831845f;   // 1/sqrt(128)

        float mn  = fmaxf(m, logit);
        float cor = __expf(m - mn);               // 0 on first edge (m = -inf)
        float w   = __expf(logit - mn);
        d  = d * cor + w;
        a0 = fmaf(w, v0, a0 * cor);
        a1 = fmaf(w, v1, a1 * cor);
        a2 = fmaf(w, v2, a2 * cor);
        a3 = fmaf(w, v3, a3 * cor);
        m = mn;
    }

    float inv = (end > beg) ? (1.0f / d) : 0.f;
    float r;
    r = fmaf(a0, inv, S[o + lane]);      hout[o + lane]      = (r > 0.f) ? r : 0.01f * r;
    r = fmaf(a1, inv, S[o + lane + 32]); hout[o + lane + 32] = (r > 0.f) ? r : 0.01f * r;
    r = fmaf(a2, inv, S[o + lane + 64]); hout[o + lane + 64] = (r > 0.f) ? r : 0.01f * r;
    r = fmaf(a3, inv, S[o + lane + 96]); hout[o + lane + 96] = (r > 0.f) ? r : 0.01f * r;
}

// ---------------- pool + MLP head ----------------
__global__ void k_zero_pool() {
    int i = blockIdx.x * blockDim.x + threadIdx.x;
    if (i < GG * CC) g_pool[i] = 0.f;
}

__global__ void k_pool(const int* __restrict__ batch) {
    int i = blockIdx.x * blockDim.x + threadIdx.x;
    if (i < NN * CC) {
        int n = i >> 7, c = i & 127;
        atomicAdd(&g_pool[batch[n] * 128 + c], g_h[i]);
    }
}

__global__ __launch_bounds__(512) void k_mlp0(const float* __restrict__ W, const float* __restrict__ b) {
    __shared__ float s[128];
    int row = blockIdx.x, t = threadIdx.x;
    if (t < 128) s[t] = g_pool[row * 128 + t];
    __syncthreads();
    float acc = b[t];
    #pragma unroll 8
    for (int k = 0; k < 128; k++) acc = fmaf(s[k], W[k * 512 + t], acc);
    g_m0[row * 512 + t] = fmaxf(acc, 0.f);
}

__global__ __launch_bounds__(256) void k_mlp1(const float* __restrict__ W, const float* __restrict__ b) {
    __shared__ float s[512];
    int row = blockIdx.x, t = threadIdx.x;
    s[t] = g_m0[row * 512 + t];
    s[t + 256] = g_m0[row * 512 + t + 256];
    __syncthreads();
    float acc = b[t];
    #pragma unroll 8
    for (int k = 0; k < 512; k++) acc = fmaf(s[k], W[k * 256 + t], acc);
    g_m1[row * 256 + t] = fmaxf(acc, 0.f);
}

__global__ __launch_bounds__(256) void k_mlp2(const float* __restrict__ W, const float* __restrict__ b,
                                              float* __restrict__ out) {
    int t = threadIdx.x;            // 256 threads = 128 rows x 2
    int row = t >> 1, p = t & 1;
    float acc = b[p];
    for (int k = 0; k < 256; k++) acc = fmaf(g_m1[row * 256 + k], W[k * 2 + p], acc);
    out[row * 2 + p] = acc;
}

// ---------------- launch ----------------
extern "C" void kernel_launch(void* const* d_in, const int* in_sizes, int n_in,
                              void* d_out, int out_size) {
    const float* x     = (const float*)d_in[0];
    const int*   ei    = (const int*)  d_in[1];
    const float* ea    = (const float*)d_in[2];
    const int*   batch = (const int*)  d_in[3];

    const float* Wq0 = (const float*)d_in[4];  const float* bq0 = (const float*)d_in[5];
    const float* Wk0 = (const float*)d_in[6];  const float* bk0 = (const float*)d_in[7];
    const float* Wv0 = (const float*)d_in[8];  const float* bv0 = (const float*)d_in[9];
    const float* We0 = (const float*)d_in[10];
    const float* Ws0 = (const float*)d_in[11]; const float* bs0 = (const float*)d_in[12];

    const float* Wq1 = (const float*)d_in[13]; const float* bq1 = (const float*)d_in[14];
    const float* Wk1 = (const float*)d_in[15]; const float* bk1 = (const float*)d_in[16];
    const float* Wv1 = (const float*)d_in[17]; const float* bv1 = (const float*)d_in[18];
    const float* We1 = (const float*)d_in[19];
    const float* Ws1 = (const float*)d_in[20]; const float* bs1 = (const float*)d_in[21];

    const float* Wl0 = (const float*)d_in[22]; const float* bl0 = (const float*)d_in[23];
    const float* Wl1 = (const float*)d_in[24]; const float* bl1 = (const float*)d_in[25];
    const float* Wl2 = (const float*)d_in[26]; const float* bl2 = (const float*)d_in[27];

    const int* srcp = ei;
    const int* dstp = ei + EE;

    // ---- CSR build (once; graph shared by all 3 layers) ----
    k_zero_deg<<<(NN + 255) / 256, 256>>>();
    k_count<<<(EE + 255) / 256, 256>>>(dstp);
    k_scan1<<<(NN + 1023) / 1024, 1024>>>();
    k_scan2<<<1, 1>>>((NN + 1023) / 1024);
    k_scan3<<<(NN + 255) / 256, 256>>>();
    k_cursor<<<(NN + 255) / 256, 256>>>();
    k_fill<<<(EE + 255) / 256, 256>>>(srcp, dstp, ea);

    dim3 gemm_grid((NN + 127) / 128, 4);
    int  agg_grid = (NN + 7) / 8;

    // ---- layer 0 ----
    k_proj0<<<(NN * 512 + 255) / 256, 256>>>(x, Wq0, bq0, Wk0, bk0, Wv0, bv0, Ws0, bs0);
    k_agg<<<agg_grid, 256>>>(We0, /*out_sel=*/0);     // -> g_h

    // ---- layer 1 (weights *1) ----
    k_sgemm<<<gemm_grid, 256>>>(0, Wq1, Wk1, Wv1, Ws1, bq1, bk1, bv1, bs1);  // g_h -> qkvs
    k_agg<<<agg_grid, 256>>>(We1, /*out_sel=*/1);     // -> g_h2

    // ---- layer 2 (same weights) ----
    k_sgemm<<<gemm_grid, 256>>>(1, Wq1, Wk1, Wv1, Ws1, bq1, bk1, bv1, bs1);  // g_h2 -> qkvs
    k_agg<<<agg_grid, 256>>>(We1, /*out_sel=*/0);     // -> g_h

    // ---- pool + MLP ----
    k_zero_pool<<<(GG * CC + 255) / 256, 256>>>();
    k_pool<<<(NN * CC + 255) / 256, 256>>>(batch);
    k_mlp0<<<GG, 512>>>(Wl0, bl0);
    k_mlp1<<<GG, 256>>>(Wl1, bl1);
    k_mlp2<<<1, 256>>>(Wl2, bl2, (float*)d_out);
}

// round 10
// speedup vs baseline: 1.2933x; 1.2933x over previous
#include <cuda_runtime.h>
#include <cuda_bf16.h>
#include <cstdint>

#define NN 50000
#define EE 800000
#define CC 128
#define GG 128
#define LD0 512
#define LD1 256
#define NC (NN*CC)

// ---------------- scratch (static device globals; no allocation) ----------------
__device__ int    g_deg[NN];
__device__ int    g_rowptr[NN + 1];
__device__ int    g_cursor[NN];
__device__ int    g_bsum[64];
__device__ int    g_boff[64];
__device__ float4 g_csr[EE];            // {src_as_float, ea0, ea1, ea2} in dst-CSR order
__device__ float  g_h[NN * CC];
__device__ float  g_h2[NN * CC];
__device__ float  g_qkvs[NN * CC * 4];  // planes: Q | K | V | S
__device__ __nv_bfloat16 g_ah[NN * CC]; // bf16 hi plane of activations
__device__ __nv_bfloat16 g_al[NN * CC]; // bf16 lo plane
__device__ __nv_bfloat16 g_bt[4 * CC * 384]; // W^T planes [mat][c][k0..383] = [Bh|Bh|Bl]
__device__ float  g_pool[GG * CC];
__device__ float  g_m0[GG * LD0];
__device__ float  g_m1[GG * LD1];

// ============================ mma.sync helpers =================================
__device__ __forceinline__ uint32_t smem_u32(const void* p) {
    uint32_t a;
    asm("{ .reg .u64 t; cvta.to.shared.u64 t, %1; cvt.u32.u64 %0, t; }" : "=r"(a) : "l"(p));
    return a;
}

__device__ __forceinline__ void ldsm_x4(uint32_t addr, uint32_t& r0, uint32_t& r1,
                                        uint32_t& r2, uint32_t& r3) {
    asm volatile("ldmatrix.sync.aligned.m8n8.x4.shared.b16 {%0,%1,%2,%3}, [%4];"
                 : "=r"(r0), "=r"(r1), "=r"(r2), "=r"(r3) : "r"(addr));
}

__device__ __forceinline__ void mma16816(float* c, const uint32_t* a, const uint32_t* b) {
    asm volatile(
        "mma.sync.aligned.m16n8k16.row.col.f32.bf16.bf16.f32 "
        "{%0,%1,%2,%3}, {%4,%5,%6,%7}, {%8,%9}, {%0,%1,%2,%3};"
        : "+f"(c[0]), "+f"(c[1]), "+f"(c[2]), "+f"(c[3])
        : "r"(a[0]), "r"(a[1]), "r"(a[2]), "r"(a[3]), "r"(b[0]), "r"(b[1]));
}

// ---------------- CSR build ----------------
__global__ void k_zero_deg() {
    int i = blockIdx.x * blockDim.x + threadIdx.x;
    if (i < NN) g_deg[i] = 0;
}

__global__ void k_count(const int* __restrict__ dst) {
    int i = blockIdx.x * blockDim.x + threadIdx.x;
    if (i < EE) atomicAdd(&g_deg[dst[i]], 1);
}

__global__ void k_scan1() {
    __shared__ int s[1024];
    int i = blockIdx.x * 1024 + threadIdx.x;
    int v = (i < NN) ? g_deg[i] : 0;
    s[threadIdx.x] = v;
    __syncthreads();
    #pragma unroll
    for (int off = 1; off < 1024; off <<= 1) {
        int t = (threadIdx.x >= off) ? s[threadIdx.x - off] : 0;
        __syncthreads();
        s[threadIdx.x] += t;
        __syncthreads();
    }
    if (i < NN) g_rowptr[i + 1] = s[threadIdx.x];
    if (threadIdx.x == 1023) g_bsum[blockIdx.x] = s[1023];
    if (i == 0) g_rowptr[0] = 0;
}

__global__ void k_scan2(int nb) {
    __shared__ int s[64];
    int t = threadIdx.x;
    s[t] = (t < nb) ? g_bsum[t] : 0;
    __syncthreads();
    if (t == 0) {
        int run = 0;
        for (int b = 0; b < nb; b++) { g_boff[b] = run; run += s[b]; }
    }
}

__global__ void k_scan3() {
    int i = blockIdx.x * blockDim.x + threadIdx.x;
    if (i < NN) g_rowptr[i + 1] += g_boff[((unsigned)i) >> 10];
}

__global__ void k_cursor() {
    int i = blockIdx.x * blockDim.x + threadIdx.x;
    if (i < NN) g_cursor[i] = g_rowptr[i];
}

__global__ void k_fill(const int* __restrict__ src, const int* __restrict__ dst,
                       const float* __restrict__ ea) {
    int i = blockIdx.x * blockDim.x + threadIdx.x;
    if (i < EE) {
        int d = dst[i];
        int p = atomicAdd(&g_cursor[d], 1);
        g_csr[p] = make_float4(__int_as_float(src[i]), ea[3 * i], ea[3 * i + 1], ea[3 * i + 2]);
    }
}

// ---------------- layer-0 projection (din = 4) ----------------
__global__ __launch_bounds__(256) void k_proj0(
    const float* __restrict__ x,
    const float* __restrict__ Wq, const float* __restrict__ bq,
    const float* __restrict__ Wk, const float* __restrict__ bk,
    const float* __restrict__ Wv, const float* __restrict__ bv,
    const float* __restrict__ Ws, const float* __restrict__ bs)
{
    int idx = blockIdx.x * 256 + threadIdx.x;
    if (idx >= NN * 512) return;
    int n  = idx >> 9;
    int c  = idx & 511;
    int mat = c >> 7, cc = c & 127;
    const float* W = (mat == 0) ? Wq : (mat == 1) ? Wk : (mat == 2) ? Wv : Ws;
    const float* b = (mat == 0) ? bq : (mat == 1) ? bk : (mat == 2) ? bv : bs;
    float x0 = x[n * 4 + 0], x1 = x[n * 4 + 1], x2 = x[n * 4 + 2], x3 = x[n * 4 + 3];
    float v = b[cc];
    v = fmaf(x0, W[cc], v);
    v = fmaf(x1, W[128 + cc], v);
    v = fmaf(x2, W[256 + cc], v);
    v = fmaf(x3, W[384 + cc], v);
    g_qkvs[mat * NC + n * 128 + cc] = v;
}

// ---------------- split fp32 activations into bf16 hi/lo planes ----------------
__global__ __launch_bounds__(256) void k_split_a(int in_sel) {
    const float* A = in_sel ? g_h2 : g_h;
    int i = blockIdx.x * 256 + threadIdx.x;     // 1 thread = 4 elems
    if (i >= NN * CC / 4) return;
    float4 v = *reinterpret_cast<const float4*>(&A[i * 4]);
    __nv_bfloat16 h0 = __float2bfloat16(v.x), h1 = __float2bfloat16(v.y);
    __nv_bfloat16 h2 = __float2bfloat16(v.z), h3 = __float2bfloat16(v.w);
    __nv_bfloat16 l0 = __float2bfloat16(v.x - __bfloat162float(h0));
    __nv_bfloat16 l1 = __float2bfloat16(v.y - __bfloat162float(h1));
    __nv_bfloat16 l2 = __float2bfloat16(v.z - __bfloat162float(h2));
    __nv_bfloat16 l3 = __float2bfloat16(v.w - __bfloat162float(h3));
    __nv_bfloat162* H = reinterpret_cast<__nv_bfloat162*>(g_ah);
    __nv_bfloat162* L = reinterpret_cast<__nv_bfloat162*>(g_al);
    H[i * 2 + 0] = __nv_bfloat162(h0, h1);
    H[i * 2 + 1] = __nv_bfloat162(h2, h3);
    L[i * 2 + 0] = __nv_bfloat162(l0, l1);
    L[i * 2 + 1] = __nv_bfloat162(l2, l3);
}

// ---------------- prep B: transpose weights into [mat][c][k 0..383] bf16 ----------------
// k<128 -> hi(W[k][c]); 128<=k<256 -> hi(W[k-128][c]); 256<=k<384 -> lo(W[k-256][c])
__global__ __launch_bounds__(256) void k_prep_b(
    const float* __restrict__ W0, const float* __restrict__ W1,
    const float* __restrict__ W2, const float* __restrict__ W3)
{
    int i = blockIdx.x * 256 + threadIdx.x;     // 4*128*384 = 196608
    if (i >= 4 * 128 * 384) return;
    int mat = i / (128 * 384);
    int rem = i % (128 * 384);
    int c = rem / 384;
    int k = rem % 384;
    const float* W = (mat == 0) ? W0 : (mat == 1) ? W1 : (mat == 2) ? W2 : W3;
    int ksrc = (k < 128) ? k : (k < 256) ? (k - 128) : (k - 256);
    float v = W[ksrc * 128 + c];
    __nv_bfloat16 out;
    if (k < 256) out = __float2bfloat16(v);
    else {
        __nv_bfloat16 h = __float2bfloat16(v);
        out = __float2bfloat16(v - __bfloat162float(h));
    }
    g_bt[mat * (128 * 384) + c * 384 + k] = out;
}

// ---------------- mma.sync split-bf16 GEMM: out[128,128] tile, K=384 ----------------
// grid (391, 4): x = M tile, y = weight matrix (Q/K/V/S).
// 256 threads = 8 warps, warp grid 2(M) x 4(N): warp tile 64x32.
// K staged in 6 chunks of 64; A planes [Ah|Al|Ah], B planes from g_bt.
#define ASTR 72   // smem row stride in bf16 (64 + 8 pad -> conflict-free ldmatrix)
__global__ __launch_bounds__(256) void k_gemm_mma(
    const float* __restrict__ b0, const float* __restrict__ b1,
    const float* __restrict__ b2, const float* __restrict__ b3)
{
    __shared__ __nv_bfloat16 sA[128 * ASTR];
    __shared__ __nv_bfloat16 sB[128 * ASTR];
    __shared__ float sbias[128];

    const int tid = threadIdx.x, wid = tid >> 5, lane = tid & 31;
    const int mat = blockIdx.y;
    const int m0 = blockIdx.x * 128;
    const __nv_bfloat16* Bt = g_bt + mat * (128 * 384);
    const float* bias = (mat == 0) ? b0 : (mat == 1) ? b1 : (mat == 2) ? b2 : b3;
    float* Out = g_qkvs + mat * NC;

    const int warpM = (wid >> 2) * 64;   // 0 or 64
    const int warpN = (wid & 3) * 32;    // 0,32,64,96

    if (tid < 128) sbias[tid] = bias[tid];

    float acc[4][4][4];
    #pragma unroll
    for (int i = 0; i < 4; i++)
        #pragma unroll
        for (int j = 0; j < 4; j++)
            #pragma unroll
            for (int k = 0; k < 4; k++) acc[i][j][k] = 0.f;

    // lane-invariant ldmatrix base offsets
    const int q = lane >> 3, r = lane & 7;
    const uint32_t sA_base = smem_u32(sA);
    const uint32_t sB_base = smem_u32(sB);
    // A: matrices (rows0-7,k0-7)(rows8-15,k0-7)(rows0-7,k8-15)(rows8-15,k8-15)
    const uint32_t a_lane = sA_base + (uint32_t)(((warpM + (q & 1) * 8 + r) * ASTR + (q >> 1) * 8) * 2);
    // B: matrices (n0-7,k0-7)(n0-7,k8-15)(n8-15,k0-7)(n8-15,k8-15)
    const uint32_t b_lane = sB_base + (uint32_t)(((warpN + (q >> 1) * 8 + r) * ASTR + (q & 1) * 8) * 2);

    for (int kc = 0; kc < 6; kc++) {
        // A chunk: plane (kc 2,3 -> lo), 64-col half = kc&1
        const __nv_bfloat16* Ap = (kc == 2 || kc == 3) ? g_al : g_ah;
        const int half = kc & 1;
        __syncthreads();
        #pragma unroll
        for (int i = 0; i < 4; i++) {
            int idx = tid + i * 256;          // 0..1023
            int row = idx >> 3, j = idx & 7;  // row 0..127, j 0..7 (uint4 per 8 bf16)
            int node = m0 + row;
            uint4 v = make_uint4(0, 0, 0, 0);
            if (node < NN) v = reinterpret_cast<const uint4*>(Ap)[node * 16 + half * 8 + j];
            *reinterpret_cast<uint4*>(&sA[row * ASTR + j * 8]) = v;
        }
        // B chunk: all 128 n-rows, k cols [kc*64, kc*64+64)
        #pragma unroll
        for (int i = 0; i < 4; i++) {
            int idx = tid + i * 256;
            int row = idx >> 3, j = idx & 7;
            uint4 v = reinterpret_cast<const uint4*>(Bt)[row * 48 + kc * 8 + j];
            *reinterpret_cast<uint4*>(&sB[row * ASTR + j * 8]) = v;
        }
        __syncthreads();

        #pragma unroll
        for (int ks = 0; ks < 4; ks++) {          // 4 k16 steps per chunk
            uint32_t af[4][4], bf[4][2];
            #pragma unroll
            for (int mi = 0; mi < 4; mi++)
                ldsm_x4(a_lane + (uint32_t)((mi * 16 * ASTR + ks * 16) * 2),
                        af[mi][0], af[mi][1], af[mi][2], af[mi][3]);
            #pragma unroll
            for (int pr = 0; pr < 2; pr++)        // n-tile pairs (0,1) and (2,3)
                ldsm_x4(b_lane + (uint32_t)((pr * 16 * ASTR + ks * 16) * 2),
                        bf[pr * 2][0], bf[pr * 2][1], bf[pr * 2 + 1][0], bf[pr * 2 + 1][1]);
            #pragma unroll
            for (int mi = 0; mi < 4; mi++)
                #pragma unroll
                for (int nj = 0; nj < 4; nj++)
                    mma16816(acc[mi][nj], af[mi], bf[nj]);
        }
    }

    // epilogue: c0,c1 -> (row, col..col+1), c2,c3 -> (row+8, col..col+1)
    const int trow = lane >> 2, tcol = 2 * (lane & 3);
    #pragma unroll
    for (int mi = 0; mi < 4; mi++) {
        int row_a = m0 + warpM + mi * 16 + trow;
        int row_b = row_a + 8;
        #pragma unroll
        for (int nj = 0; nj < 4; nj++) {
            int col = warpN + nj * 8 + tcol;
            if (row_a < NN) {
                float2 o;
                o.x = acc[mi][nj][0] + sbias[col];
                o.y = acc[mi][nj][1] + sbias[col + 1];
                *reinterpret_cast<float2*>(&Out[row_a * 128 + col]) = o;
            }
            if (row_b < NN) {
                float2 o;
                o.x = acc[mi][nj][2] + sbias[col];
                o.y = acc[mi][nj][3] + sbias[col + 1];
                *reinterpret_cast<float2*>(&Out[row_b * 128 + col]) = o;
            }
        }
    }
}

// ---------------- warp-per-node online-softmax aggregation (float4 lanes) ----------------
__global__ __launch_bounds__(256) void k_agg(const float* __restrict__ We, int out_sel)
{
    __shared__ float sWe[384];
    for (int i = threadIdx.x; i < 384; i += 256) sWe[i] = We[i];
    __syncthreads();

    int warp = threadIdx.x >> 5, lane = threadIdx.x & 31;
    int node = blockIdx.x * 8 + warp;
    if (node >= NN) return;

    float* hout = out_sel ? g_h2 : g_h;
    const float* Q = g_qkvs;
    const float* K = g_qkvs + NC;
    const float* V = g_qkvs + 2 * NC;
    const float* S = g_qkvs + 3 * NC;

    int o = node * 128;
    int c4 = lane * 4;
    float4 q  = *reinterpret_cast<const float4*>(Q + o + c4);
    float4 w0 = *reinterpret_cast<const float4*>(sWe + c4);
    float4 w1 = *reinterpret_cast<const float4*>(sWe + 128 + c4);
    float4 w2 = *reinterpret_cast<const float4*>(sWe + 256 + c4);

    const float NEG_INF = __int_as_float(0xff800000);
    float m = NEG_INF, d = 0.f;
    float4 a = make_float4(0.f, 0.f, 0.f, 0.f);

    int beg = g_rowptr[node], end = g_rowptr[node + 1];

    for (int e = beg; e < end; e++) {
        float4 ed = g_csr[e];
        int src = __float_as_int(ed.x);
        float4 kv = *reinterpret_cast<const float4*>(K + src * 128 + c4);
        float4 vv = *reinterpret_cast<const float4*>(V + src * 128 + c4);

        float e0 = fmaf(ed.y, w0.x, fmaf(ed.z, w1.x, ed.w * w2.x));
        float e1 = fmaf(ed.y, w0.y, fmaf(ed.z, w1.y, ed.w * w2.y));
        float e2 = fmaf(ed.y, w0.z, fmaf(ed.z, w1.z, ed.w * w2.z));
        float e3 = fmaf(ed.y, w0.w, fmaf(ed.z, w1.w, ed.w * w2.w));

        kv.x += e0; kv.y += e1; kv.z += e2; kv.w += e3;
        vv.x += e0; vv.y += e1; vv.z += e2; vv.w += e3;

        float p = fmaf(q.x, kv.x, fmaf(q.y, kv.y, fmaf(q.z, kv.z, q.w * kv.w)));
        p += __shfl_xor_sync(0xffffffffu, p, 16);
        p += __shfl_xor_sync(0xffffffffu, p, 8);
        p += __shfl_xor_sync(0xffffffffu, p, 4);
        p += __shfl_xor_sync(0xffffffffu, p, 2);
        p += __shfl_xor_sync(0xffffffffu, p, 1);
        float logit = p * 0.08838834764831845f;   // 1/sqrt(128)

        float mn  = fmaxf(m, logit);
        float cor = __expf(m - mn);               // 0 on first edge (m = -inf)
        float w   = __expf(logit - mn);
        d   = d * cor + w;
        a.x = fmaf(w, vv.x, a.x * cor);
        a.y = fmaf(w, vv.y, a.y * cor);
        a.z = fmaf(w, vv.z, a.z * cor);
        a.w = fmaf(w, vv.w, a.w * cor);
        m = mn;
    }

    float inv = (end > beg) ? (1.0f / d) : 0.f;
    float4 s = *reinterpret_cast<const float4*>(S + o + c4);
    float4 r;
    r.x = fmaf(a.x, inv, s.x); r.x = (r.x > 0.f) ? r.x : 0.01f * r.x;
    r.y = fmaf(a.y, inv, s.y); r.y = (r.y > 0.f) ? r.y : 0.01f * r.y;
    r.z = fmaf(a.z, inv, s.z); r.z = (r.z > 0.f) ? r.z : 0.01f * r.z;
    r.w = fmaf(a.w, inv, s.w); r.w = (r.w > 0.f) ? r.w : 0.01f * r.w;
    *reinterpret_cast<float4*>(hout + o + c4) = r;
}

// ---------------- pool (sorted batch -> segmented reduce, no atomics) ----------------
__global__ __launch_bounds__(128) void k_pool2(const int* __restrict__ batch) {
    int g = blockIdx.x, t = threadIdx.x;
    int lo = 0, hi = NN;
    while (lo < hi) { int mid = (lo + hi) >> 1; if (batch[mid] < g) lo = mid + 1; else hi = mid; }
    int beg = lo;
    hi = NN;
    while (lo < hi) { int mid = (lo + hi) >> 1; if (batch[mid] < g + 1) lo = mid + 1; else hi = mid; }
    int end = lo;
    float acc = 0.f;
    for (int r = beg; r < end; r++) acc += g_h[r * 128 + t];
    g_pool[g * 128 + t] = acc;
}

// ---------------- MLP head ----------------
__global__ __launch_bounds__(512) void k_mlp0(const float* __restrict__ W, const float* __restrict__ b) {
    __shared__ float s[128];
    int row = blockIdx.x, t = threadIdx.x;
    if (t < 128) s[t] = g_pool[row * 128 + t];
    __syncthreads();
    float acc = b[t];
    #pragma unroll 8
    for (int k = 0; k < 128; k++) acc = fmaf(s[k], W[k * 512 + t], acc);
    g_m0[row * 512 + t] = fmaxf(acc, 0.f);
}

__global__ __launch_bounds__(256) void k_mlp1(const float* __restrict__ W, const float* __restrict__ b) {
    __shared__ float s[512];
    int row = blockIdx.x, t = threadIdx.x;
    s[t] = g_m0[row * 512 + t];
    s[t + 256] = g_m0[row * 512 + t + 256];
    __syncthreads();
    float acc = b[t];
    #pragma unroll 8
    for (int k = 0; k < 512; k++) acc = fmaf(s[k], W[k * 256 + t], acc);
    g_m1[row * 256 + t] = fmaxf(acc, 0.f);
}

__global__ __launch_bounds__(256) void k_mlp2(const float* __restrict__ W, const float* __restrict__ b,
                                              float* __restrict__ out) {
    int t = threadIdx.x;
    int row = t >> 1, p = t & 1;
    float acc = b[p];
    for (int k = 0; k < 256; k++) acc = fmaf(g_m1[row * 256 + k], W[k * 2 + p], acc);
    out[row * 2 + p] = acc;
}

// ---------------- launch ----------------
extern "C" void kernel_launch(void* const* d_in, const int* in_sizes, int n_in,
                              void* d_out, int out_size) {
    const float* x     = (const float*)d_in[0];
    const int*   ei    = (const int*)  d_in[1];
    const float* ea    = (const float*)d_in[2];
    const int*   batch = (const int*)  d_in[3];

    const float* Wq0 = (const float*)d_in[4];  const float* bq0 = (const float*)d_in[5];
    const float* Wk0 = (const float*)d_in[6];  const float* bk0 = (const float*)d_in[7];
    const float* Wv0 = (const float*)d_in[8];  const float* bv0 = (const float*)d_in[9];
    const float* We0 = (const float*)d_in[10];
    const float* Ws0 = (const float*)d_in[11]; const float* bs0 = (const float*)d_in[12];

    const float* Wq1 = (const float*)d_in[13]; const float* bq1 = (const float*)d_in[14];
    const float* Wk1 = (const float*)d_in[15]; const float* bk1 = (const float*)d_in[16];
    const float* Wv1 = (const float*)d_in[17]; const float* bv1 = (const float*)d_in[18];
    const float* We1 = (const float*)d_in[19];
    const float* Ws1 = (const float*)d_in[20]; const float* bs1 = (const float*)d_in[21];

    const float* Wl0 = (const float*)d_in[22]; const float* bl0 = (const float*)d_in[23];
    const float* Wl1 = (const float*)d_in[24]; const float* bl1 = (const float*)d_in[25];
    const float* Wl2 = (const float*)d_in[26]; const float* bl2 = (const float*)d_in[27];

    const int* srcp = ei;
    const int* dstp = ei + EE;

    // ---- CSR build (once; graph shared by all 3 layers) ----
    k_zero_deg<<<(NN + 255) / 256, 256>>>();
    k_count<<<(EE + 255) / 256, 256>>>(dstp);
    k_scan1<<<(NN + 1023) / 1024, 1024>>>();
    k_scan2<<<1, 64>>>((NN + 1023) / 1024);
    k_scan3<<<(NN + 255) / 256, 256>>>();
    k_cursor<<<(NN + 255) / 256, 256>>>();
    k_fill<<<(EE + 255) / 256, 256>>>(srcp, dstp, ea);

    // ---- prep transposed bf16 weight planes (layers 1&2 share weights) ----
    k_prep_b<<<(4 * 128 * 384 + 255) / 256, 256>>>(Wq1, Wk1, Wv1, Ws1);

    dim3 gemm_grid((NN + 127) / 128, 4);
    int  agg_grid = (NN + 7) / 8;
    int  split_grid = (NN * CC / 4 + 255) / 256;

    // ---- layer 0 ----
    k_proj0<<<(NN * 512 + 255) / 256, 256>>>(x, Wq0, bq0, Wk0, bk0, Wv0, bv0, Ws0, bs0);
    k_agg<<<agg_grid, 256>>>(We0, /*out_sel=*/0);      // -> g_h

    // ---- layer 1 ----
    k_split_a<<<split_grid, 256>>>(0);                  // g_h -> g_ah/g_al
    k_gemm_mma<<<gemm_grid, 256>>>(bq1, bk1, bv1, bs1); // -> g_qkvs
    k_agg<<<agg_grid, 256>>>(We1, /*out_sel=*/1);       // -> g_h2

    // ---- layer 2 (same weights) ----
    k_split_a<<<split_grid, 256>>>(1);                  // g_h2 -> g_ah/g_al
    k_gemm_mma<<<gemm_grid, 256>>>(bq1, bk1, bv1, bs1); // -> g_qkvs
    k_agg<<<agg_grid, 256>>>(We1, /*out_sel=*/0);       // -> g_h

    // ---- pool + MLP ----
    k_pool2<<<GG, 128>>>(batch);
    k_mlp0<<<GG, 512>>>(Wl0, bl0);
    k_mlp1<<<GG, 256>>>(Wl1, bl1);
    k_mlp2<<<1, 256>>>(Wl2, bl2, (float*)d_out);
}

// round 11
// speedup vs baseline: 1.5332x; 1.1855x over previous
#include <cuda_runtime.h>
#include <cuda_bf16.h>
#include <cuda_fp16.h>
#include <cstdint>

#define NN 50000
#define EE 800000
#define CC 128
#define GG 128
#define LD0 512
#define LD1 256
#define NC (NN*CC)

// ---------------- scratch (static device globals; no allocation) ----------------
__device__ int    g_deg[NN];
__device__ int    g_rowptr[NN + 1];
__device__ int    g_cursor[NN];
__device__ int    g_bsum[64];
__device__ int    g_boff[64];
__device__ float4 g_csr[EE];            // {src_as_float, ea0, ea1, ea2} in dst-CSR order
__device__ float  g_h[NN * CC];         // final-layer fp32 output (for pool)
__device__ float  g_q[NN * CC];         // Q plane fp32
__device__ float  g_s[NN * CC];         // S (skip) plane fp32
__device__ __half2 g_kh[NN * CC / 2];   // K plane fp16
__device__ __half2 g_vh[NN * CC / 2];   // V plane fp16
__device__ __nv_bfloat16 g_ah[NN * CC]; // bf16 hi plane of activations
__device__ __nv_bfloat16 g_al[NN * CC]; // bf16 lo plane
__device__ __nv_bfloat16 g_bt[4 * CC * 384]; // W^T planes [mat][c][k0..383] = [Bh|Bh|Bl]
__device__ float  g_pool[GG * CC];
__device__ float  g_m0[GG * LD0];
__device__ float  g_m1[GG * LD1];

// ============================ mma.sync helpers =================================
__device__ __forceinline__ uint32_t smem_u32(const void* p) {
    uint32_t a;
    asm("{ .reg .u64 t; cvta.to.shared.u64 t, %1; cvt.u32.u64 %0, t; }" : "=r"(a) : "l"(p));
    return a;
}

__device__ __forceinline__ void ldsm_x4(uint32_t addr, uint32_t& r0, uint32_t& r1,
                                        uint32_t& r2, uint32_t& r3) {
    asm volatile("ldmatrix.sync.aligned.m8n8.x4.shared.b16 {%0,%1,%2,%3}, [%4];"
                 : "=r"(r0), "=r"(r1), "=r"(r2), "=r"(r3) : "r"(addr));
}

__device__ __forceinline__ void mma16816(float* c, const uint32_t* a, const uint32_t* b) {
    asm volatile(
        "mma.sync.aligned.m16n8k16.row.col.f32.bf16.bf16.f32 "
        "{%0,%1,%2,%3}, {%4,%5,%6,%7}, {%8,%9}, {%0,%1,%2,%3};"
        : "+f"(c[0]), "+f"(c[1]), "+f"(c[2]), "+f"(c[3])
        : "r"(a[0]), "r"(a[1]), "r"(a[2]), "r"(a[3]), "r"(b[0]), "r"(b[1]));
}

// ---------------- CSR build ----------------
__global__ void k_zero_deg() {
    int i = blockIdx.x * blockDim.x + threadIdx.x;
    if (i < NN) g_deg[i] = 0;
}

__global__ void k_count(const int* __restrict__ dst) {
    int i = blockIdx.x * blockDim.x + threadIdx.x;
    if (i < EE) atomicAdd(&g_deg[dst[i]], 1);
}

__global__ void k_scan1() {
    __shared__ int s[1024];
    int i = blockIdx.x * 1024 + threadIdx.x;
    int v = (i < NN) ? g_deg[i] : 0;
    s[threadIdx.x] = v;
    __syncthreads();
    #pragma unroll
    for (int off = 1; off < 1024; off <<= 1) {
        int t = (threadIdx.x >= off) ? s[threadIdx.x - off] : 0;
        __syncthreads();
        s[threadIdx.x] += t;
        __syncthreads();
    }
    if (i < NN) g_rowptr[i + 1] = s[threadIdx.x];
    if (threadIdx.x == 1023) g_bsum[blockIdx.x] = s[1023];
    if (i == 0) g_rowptr[0] = 0;
}

__global__ void k_scan2(int nb) {
    __shared__ int s[64];
    int t = threadIdx.x;
    s[t] = (t < nb) ? g_bsum[t] : 0;
    __syncthreads();
    if (t == 0) {
        int run = 0;
        for (int b = 0; b < nb; b++) { g_boff[b] = run; run += s[b]; }
    }
}

__global__ void k_scan3() {
    int i = blockIdx.x * blockDim.x + threadIdx.x;
    if (i < NN) g_rowptr[i + 1] += g_boff[((unsigned)i) >> 10];
}

__global__ void k_cursor() {
    int i = blockIdx.x * blockDim.x + threadIdx.x;
    if (i < NN) g_cursor[i] = g_rowptr[i];
}

__global__ void k_fill(const int* __restrict__ src, const int* __restrict__ dst,
                       const float* __restrict__ ea) {
    int i = blockIdx.x * blockDim.x + threadIdx.x;
    if (i < EE) {
        int d = dst[i];
        int p = atomicAdd(&g_cursor[d], 1);
        g_csr[p] = make_float4(__int_as_float(src[i]), ea[3 * i], ea[3 * i + 1], ea[3 * i + 2]);
    }
}

// ---------------- layer-0 projection (din = 4) ----------------
__global__ __launch_bounds__(256) void k_proj0(
    const float* __restrict__ x,
    const float* __restrict__ Wq, const float* __restrict__ bq,
    const float* __restrict__ Wk, const float* __restrict__ bk,
    const float* __restrict__ Wv, const float* __restrict__ bv,
    const float* __restrict__ Ws, const float* __restrict__ bs)
{
    int idx = blockIdx.x * 256 + threadIdx.x;
    if (idx >= NN * 512) return;
    int n  = idx >> 9;
    int c  = idx & 511;
    int mat = c >> 7, cc = c & 127;
    const float* W = (mat == 0) ? Wq : (mat == 1) ? Wk : (mat == 2) ? Wv : Ws;
    const float* b = (mat == 0) ? bq : (mat == 1) ? bk : (mat == 2) ? bv : bs;
    float x0 = x[n * 4 + 0], x1 = x[n * 4 + 1], x2 = x[n * 4 + 2], x3 = x[n * 4 + 3];
    float v = b[cc];
    v = fmaf(x0, W[cc], v);
    v = fmaf(x1, W[128 + cc], v);
    v = fmaf(x2, W[256 + cc], v);
    v = fmaf(x3, W[384 + cc], v);
    if (mat == 0)      g_q[n * 128 + cc] = v;
    else if (mat == 1) ((__half*)g_kh)[n * 128 + cc] = __float2half_rn(v);
    else if (mat == 2) ((__half*)g_vh)[n * 128 + cc] = __float2half_rn(v);
    else               g_s[n * 128 + cc] = v;
}

// ---------------- prep B: transpose weights into [mat][c][k 0..383] bf16 ----------------
__global__ __launch_bounds__(256) void k_prep_b(
    const float* __restrict__ W0, const float* __restrict__ W1,
    const float* __restrict__ W2, const float* __restrict__ W3)
{
    int i = blockIdx.x * 256 + threadIdx.x;     // 4*128*384 = 196608
    if (i >= 4 * 128 * 384) return;
    int mat = i / (128 * 384);
    int rem = i % (128 * 384);
    int c = rem / 384;
    int k = rem % 384;
    const float* W = (mat == 0) ? W0 : (mat == 1) ? W1 : (mat == 2) ? W2 : W3;
    int ksrc = (k < 128) ? k : (k < 256) ? (k - 128) : (k - 256);
    float v = W[ksrc * 128 + c];
    __nv_bfloat16 out;
    if (k < 256) out = __float2bfloat16(v);
    else {
        __nv_bfloat16 h = __float2bfloat16(v);
        out = __float2bfloat16(v - __bfloat162float(h));
    }
    g_bt[mat * (128 * 384) + c * 384 + k] = out;
}

// ---------------- mma.sync split-bf16 GEMM: out[128,128] tile, K=384 ----------------
// grid (391, 4): x = M tile, y = weight matrix (Q/K/V/S).
// 256 threads = 8 warps, warp grid 2(M) x 4(N): warp tile 64x32.
// A always read from g_ah/g_al planes (filled by proj0-agg or previous agg).
#define ASTR 72
__global__ __launch_bounds__(256) void k_gemm_mma(
    const float* __restrict__ b0, const float* __restrict__ b1,
    const float* __restrict__ b2, const float* __restrict__ b3)
{
    __shared__ __nv_bfloat16 sA[128 * ASTR];
    __shared__ __nv_bfloat16 sB[128 * ASTR];
    __shared__ float sbias[128];

    const int tid = threadIdx.x, wid = tid >> 5, lane = tid & 31;
    const int mat = blockIdx.y;
    const int m0 = blockIdx.x * 128;
    const __nv_bfloat16* Bt = g_bt + mat * (128 * 384);
    const float* bias = (mat == 0) ? b0 : (mat == 1) ? b1 : (mat == 2) ? b2 : b3;

    const int warpM = (wid >> 2) * 64;
    const int warpN = (wid & 3) * 32;

    if (tid < 128) sbias[tid] = bias[tid];

    float acc[4][4][4];
    #pragma unroll
    for (int i = 0; i < 4; i++)
        #pragma unroll
        for (int j = 0; j < 4; j++)
            #pragma unroll
            for (int k = 0; k < 4; k++) acc[i][j][k] = 0.f;

    const int q = lane >> 3, r = lane & 7;
    const uint32_t sA_base = smem_u32(sA);
    const uint32_t sB_base = smem_u32(sB);
    const uint32_t a_lane = sA_base + (uint32_t)(((warpM + (q & 1) * 8 + r) * ASTR + (q >> 1) * 8) * 2);
    const uint32_t b_lane = sB_base + (uint32_t)(((warpN + (q >> 1) * 8 + r) * ASTR + (q & 1) * 8) * 2);

    for (int kc = 0; kc < 6; kc++) {
        const __nv_bfloat16* Ap = (kc == 2 || kc == 3) ? g_al : g_ah;
        const int half = kc & 1;
        __syncthreads();
        #pragma unroll
        for (int i = 0; i < 4; i++) {
            int idx = tid + i * 256;
            int row = idx >> 3, j = idx & 7;
            int node = m0 + row;
            uint4 v = make_uint4(0, 0, 0, 0);
            if (node < NN) v = reinterpret_cast<const uint4*>(Ap)[node * 16 + half * 8 + j];
            *reinterpret_cast<uint4*>(&sA[row * ASTR + j * 8]) = v;
        }
        #pragma unroll
        for (int i = 0; i < 4; i++) {
            int idx = tid + i * 256;
            int row = idx >> 3, j = idx & 7;
            uint4 v = reinterpret_cast<const uint4*>(Bt)[row * 48 + kc * 8 + j];
            *reinterpret_cast<uint4*>(&sB[row * ASTR + j * 8]) = v;
        }
        __syncthreads();

        #pragma unroll
        for (int ks = 0; ks < 4; ks++) {
            uint32_t af[4][4], bf[4][2];
            #pragma unroll
            for (int mi = 0; mi < 4; mi++)
                ldsm_x4(a_lane + (uint32_t)((mi * 16 * ASTR + ks * 16) * 2),
                        af[mi][0], af[mi][1], af[mi][2], af[mi][3]);
            #pragma unroll
            for (int pr = 0; pr < 2; pr++)
                ldsm_x4(b_lane + (uint32_t)((pr * 16 * ASTR + ks * 16) * 2),
                        bf[pr * 2][0], bf[pr * 2][1], bf[pr * 2 + 1][0], bf[pr * 2 + 1][1]);
            #pragma unroll
            for (int mi = 0; mi < 4; mi++)
                #pragma unroll
                for (int nj = 0; nj < 4; nj++)
                    mma16816(acc[mi][nj], af[mi], bf[nj]);
        }
    }

    // epilogue: Q/S -> fp32, K/V -> fp16
    const int trow = lane >> 2, tcol = 2 * (lane & 3);
    const bool is_half = (mat == 1 || mat == 2);
    float*   Outf = (mat == 0) ? g_q : g_s;
    __half2* Outh = (mat == 1) ? g_kh : g_vh;
    #pragma unroll
    for (int mi = 0; mi < 4; mi++) {
        int row_a = m0 + warpM + mi * 16 + trow;
        int row_b = row_a + 8;
        #pragma unroll
        for (int nj = 0; nj < 4; nj++) {
            int col = warpN + nj * 8 + tcol;
            float bx = sbias[col], by = sbias[col + 1];
            if (row_a < NN) {
                float ox = acc[mi][nj][0] + bx, oy = acc[mi][nj][1] + by;
                if (is_half) Outh[row_a * 64 + (col >> 1)] = __floats2half2_rn(ox, oy);
                else *reinterpret_cast<float2*>(&Outf[row_a * 128 + col]) = make_float2(ox, oy);
            }
            if (row_b < NN) {
                float ox = acc[mi][nj][2] + bx, oy = acc[mi][nj][3] + by;
                if (is_half) Outh[row_b * 64 + (col >> 1)] = __floats2half2_rn(ox, oy);
                else *reinterpret_cast<float2*>(&Outf[row_b * 128 + col]) = make_float2(ox, oy);
            }
        }
    }
}

// ---------------- warp-per-node aggregation (fp16 gathers, no-max softmax) -------
// mode 0: write bf16 hi/lo planes (feeds next GEMM). mode 1: write fp32 g_h (pool).
__global__ __launch_bounds__(256) void k_agg(const float* __restrict__ We, int mode)
{
    __shared__ float sWe[384];
    for (int i = threadIdx.x; i < 384; i += 256) sWe[i] = We[i];
    __syncthreads();

    int warp = threadIdx.x >> 5, lane = threadIdx.x & 31;
    int node = blockIdx.x * 8 + warp;
    if (node >= NN) return;

    int o = node * 128;
    int c4 = lane * 4;
    float4 q  = *reinterpret_cast<const float4*>(g_q + o + c4);
    float4 w0 = *reinterpret_cast<const float4*>(sWe + c4);
    float4 w1 = *reinterpret_cast<const float4*>(sWe + 128 + c4);
    float4 w2 = *reinterpret_cast<const float4*>(sWe + 256 + c4);

    float d = 0.f;
    float4 a = make_float4(0.f, 0.f, 0.f, 0.f);

    int beg = g_rowptr[node], end = g_rowptr[node + 1];

    #pragma unroll 2
    for (int e = beg; e < end; e++) {
        float4 ed = g_csr[e];
        int src = __float_as_int(ed.x);
        // 4 channels per lane, fp16: two half2 = 8 bytes
        uint2 kr = *reinterpret_cast<const uint2*>(g_kh + src * 64 + lane * 2);
        uint2 vr = *reinterpret_cast<const uint2*>(g_vh + src * 64 + lane * 2);
        float2 k01 = __half22float2(*reinterpret_cast<__half2*>(&kr.x));
        float2 k23 = __half22float2(*reinterpret_cast<__half2*>(&kr.y));
        float2 v01 = __half22float2(*reinterpret_cast<__half2*>(&vr.x));
        float2 v23 = __half22float2(*reinterpret_cast<__half2*>(&vr.y));

        float e0 = fmaf(ed.y, w0.x, fmaf(ed.z, w1.x, ed.w * w2.x));
        float e1 = fmaf(ed.y, w0.y, fmaf(ed.z, w1.y, ed.w * w2.y));
        float e2 = fmaf(ed.y, w0.z, fmaf(ed.z, w1.z, ed.w * w2.z));
        float e3 = fmaf(ed.y, w0.w, fmaf(ed.z, w1.w, ed.w * w2.w));

        float k0 = k01.x + e0, k1 = k01.y + e1, k2 = k23.x + e2, k3 = k23.y + e3;
        float v0 = v01.x + e0, v1 = v01.y + e1, v2 = v23.x + e2, v3 = v23.y + e3;

        float p = fmaf(q.x, k0, fmaf(q.y, k1, fmaf(q.z, k2, q.w * k3)));
        p += __shfl_xor_sync(0xffffffffu, p, 16);
        p += __shfl_xor_sync(0xffffffffu, p, 8);
        p += __shfl_xor_sync(0xffffffffu, p, 4);
        p += __shfl_xor_sync(0xffffffffu, p, 2);
        p += __shfl_xor_sync(0xffffffffu, p, 1);
        // no max-subtraction: fp32 exp range is ample; ratios identical
        float w = __expf(p * 0.08838834764831845f);
        d += w;
        a.x = fmaf(w, v0, a.x);
        a.y = fmaf(w, v1, a.y);
        a.z = fmaf(w, v2, a.z);
        a.w = fmaf(w, v3, a.w);
    }

    float inv = (end > beg) ? (1.0f / fmaxf(d, 1e-35f)) : 0.f;
    float4 s = *reinterpret_cast<const float4*>(g_s + o + c4);
    float4 r;
    r.x = fmaf(a.x, inv, s.x); r.x = (r.x > 0.f) ? r.x : 0.01f * r.x;
    r.y = fmaf(a.y, inv, s.y); r.y = (r.y > 0.f) ? r.y : 0.01f * r.y;
    r.z = fmaf(a.z, inv, s.z); r.z = (r.z > 0.f) ? r.z : 0.01f * r.z;
    r.w = fmaf(a.w, inv, s.w); r.w = (r.w > 0.f) ? r.w : 0.01f * r.w;

    if (mode == 0) {
        // fused bf16 hi/lo split for the next GEMM
        __nv_bfloat16 h0 = __float2bfloat16(r.x), h1 = __float2bfloat16(r.y);
        __nv_bfloat16 h2 = __float2bfloat16(r.z), h3 = __float2bfloat16(r.w);
        __nv_bfloat16 l0 = __float2bfloat16(r.x - __bfloat162float(h0));
        __nv_bfloat16 l1 = __float2bfloat16(r.y - __bfloat162float(h1));
        __nv_bfloat16 l2 = __float2bfloat16(r.z - __bfloat162float(h2));
        __nv_bfloat16 l3 = __float2bfloat16(r.w - __bfloat162float(h3));
        __nv_bfloat162 hh0(h0, h1), hh1(h2, h3), ll0(l0, l1), ll1(l2, l3);
        uint2 hv, lv;
        hv.x = *reinterpret_cast<uint32_t*>(&hh0); hv.y = *reinterpret_cast<uint32_t*>(&hh1);
        lv.x = *reinterpret_cast<uint32_t*>(&ll0); lv.y = *reinterpret_cast<uint32_t*>(&ll1);
        *reinterpret_cast<uint2*>(g_ah + o + c4) = hv;
        *reinterpret_cast<uint2*>(g_al + o + c4) = lv;
    } else {
        *reinterpret_cast<float4*>(g_h + o + c4) = r;
    }
}

// ---------------- pool (sorted batch -> segmented reduce, no atomics) ----------------
__global__ __launch_bounds__(128) void k_pool2(const int* __restrict__ batch) {
    int g = blockIdx.x, t = threadIdx.x;
    int lo = 0, hi = NN;
    while (lo < hi) { int mid = (lo + hi) >> 1; if (batch[mid] < g) lo = mid + 1; else hi = mid; }
    int beg = lo;
    hi = NN;
    while (lo < hi) { int mid = (lo + hi) >> 1; if (batch[mid] < g + 1) lo = mid + 1; else hi = mid; }
    int end = lo;
    float acc = 0.f;
    for (int r = beg; r < end; r++) acc += g_h[r * 128 + t];
    g_pool[g * 128 + t] = acc;
}

// ---------------- MLP head ----------------
__global__ __launch_bounds__(512) void k_mlp0(const float* __restrict__ W, const float* __restrict__ b) {
    __shared__ float s[128];
    int row = blockIdx.x, t = threadIdx.x;
    if (t < 128) s[t] = g_pool[row * 128 + t];
    __syncthreads();
    float acc = b[t];
    #pragma unroll 8
    for (int k = 0; k < 128; k++) acc = fmaf(s[k], W[k * 512 + t], acc);
    g_m0[row * 512 + t] = fmaxf(acc, 0.f);
}

__global__ __launch_bounds__(256) void k_mlp1(const float* __restrict__ W, const float* __restrict__ b) {
    __shared__ float s[512];
    int row = blockIdx.x, t = threadIdx.x;
    s[t] = g_m0[row * 512 + t];
    s[t + 256] = g_m0[row * 512 + t + 256];
    __syncthreads();
    float acc = b[t];
    #pragma unroll 8
    for (int k = 0; k < 512; k++) acc = fmaf(s[k], W[k * 256 + t], acc);
    g_m1[row * 256 + t] = fmaxf(acc, 0.f);
}

__global__ __launch_bounds__(256) void k_mlp2(const float* __restrict__ W, const float* __restrict__ b,
                                              float* __restrict__ out) {
    int t = threadIdx.x;
    int row = t >> 1, p = t & 1;
    float acc = b[p];
    for (int k = 0; k < 256; k++) acc = fmaf(g_m1[row * 256 + k], W[k * 2 + p], acc);
    out[row * 2 + p] = acc;
}

// ---------------- launch ----------------
extern "C" void kernel_launch(void* const* d_in, const int* in_sizes, int n_in,
                              void* d_out, int out_size) {
    const float* x     = (const float*)d_in[0];
    const int*   ei    = (const int*)  d_in[1];
    const float* ea    = (const float*)d_in[2];
    const int*   batch = (const int*)  d_in[3];

    const float* Wq0 = (const float*)d_in[4];  const float* bq0 = (const float*)d_in[5];
    const float* Wk0 = (const float*)d_in[6];  const float* bk0 = (const float*)d_in[7];
    const float* Wv0 = (const float*)d_in[8];  const float* bv0 = (const float*)d_in[9];
    const float* We0 = (const float*)d_in[10];
    const float* Ws0 = (const float*)d_in[11]; const float* bs0 = (const float*)d_in[12];

    const float* Wq1 = (const float*)d_in[13]; const float* bq1 = (const float*)d_in[14];
    const float* Wk1 = (const float*)d_in[15]; const float* bk1 = (const float*)d_in[16];
    const float* Wv1 = (const float*)d_in[17]; const float* bv1 = (const float*)d_in[18];
    const float* We1 = (const float*)d_in[19];
    const float* Ws1 = (const float*)d_in[20]; const float* bs1 = (const float*)d_in[21];

    const float* Wl0 = (const float*)d_in[22]; const float* bl0 = (const float*)d_in[23];
    const float* Wl1 = (const float*)d_in[24]; const float* bl1 = (const float*)d_in[25];
    const float* Wl2 = (const float*)d_in[26]; const float* bl2 = (const float*)d_in[27];

    const int* srcp = ei;
    const int* dstp = ei + EE;

    // ---- CSR build (once; graph shared by all 3 layers) ----
    k_zero_deg<<<(NN + 255) / 256, 256>>>();
    k_count<<<(EE + 255) / 256, 256>>>(dstp);
    k_scan1<<<(NN + 1023) / 1024, 1024>>>();
    k_scan2<<<1, 64>>>((NN + 1023) / 1024);
    k_scan3<<<(NN + 255) / 256, 256>>>();
    k_cursor<<<(NN + 255) / 256, 256>>>();
    k_fill<<<(EE + 255) / 256, 256>>>(srcp, dstp, ea);

    // ---- prep transposed bf16 weight planes (layers 1&2 share weights) ----
    k_prep_b<<<(4 * 128 * 384 + 255) / 256, 256>>>(Wq1, Wk1, Wv1, Ws1);

    dim3 gemm_grid((NN + 127) / 128, 4);
    int  agg_grid = (NN + 7) / 8;

    // ---- layer 0 ----
    k_proj0<<<(NN * 512 + 255) / 256, 256>>>(x, Wq0, bq0, Wk0, bk0, Wv0, bv0, Ws0, bs0);
    k_agg<<<agg_grid, 256>>>(We0, /*mode=*/0);          // -> g_ah/g_al

    // ---- layer 1 ----
    k_gemm_mma<<<gemm_grid, 256>>>(bq1, bk1, bv1, bs1); // planes -> Q/K/V/S
    k_agg<<<agg_grid, 256>>>(We1, /*mode=*/0);          // -> g_ah/g_al

    // ---- layer 2 (same weights) ----
    k_gemm_mma<<<gemm_grid, 256>>>(bq1, bk1, bv1, bs1); // planes -> Q/K/V/S
    k_agg<<<agg_grid, 256>>>(We1, /*mode=*/1);          // -> g_h (fp32)

    // ---- pool + MLP ----
    k_pool2<<<GG, 128>>>(batch);
    k_mlp0<<<GG, 512>>>(Wl0, bl0);
    k_mlp1<<<GG, 256>>>(Wl1, bl1);
    k_mlp2<<<1, 256>>>(Wl2, bl2, (float*)d_out);
}